// round 2
// baseline (speedup 1.0000x reference)
#include <cuda_runtime.h>
#include <cstdint>

#define BATCH 256
#define QNUM 900
#define CNUM 91
#define QC (QNUM * CNUM)       // 81900
#define NV (QC / 4)            // 20475 float4 per row
#define K_SEL 100
#define CAPC 1024
#define THR 2.75f
#define SEGS 8
#define SEG_F4 2560            // ceil(20475/8)
#define SCAN_T 256
#define POST_T 256

__device__ int g_cnt[BATCH];                         // zero-init at module load; reset by post_kernel
__device__ unsigned long long g_cand[BATCH * CAPC];  // 2 MB scratch

// monotone float<->uint mapping (order-preserving)
__device__ __forceinline__ uint32_t mono(float f) {
    uint32_t u = __float_as_uint(f);
    return u ^ ((u >> 31) ? 0xFFFFFFFFu : 0x80000000u);
}
__device__ __forceinline__ float unmono(uint32_t m) {
    uint32_t u = (m & 0x80000000u) ? (m ^ 0x80000000u) : ~m;
    return __uint_as_float(u);
}

// ---------------- Phase 1: full-chip streaming scan ----------------
__global__ __launch_bounds__(SCAN_T)
void scan_kernel(const float* __restrict__ logits)
{
    const int c = blockIdx.x;
    const int b = c >> 3;          // row
    const int s = c & 7;           // segment
    const float4* row = (const float4*)(logits + (size_t)b * QC);
    const int end = min((s + 1) * SEG_F4, NV);

    #pragma unroll 4
    for (int i = s * SEG_F4 + threadIdx.x; i < end; i += SCAN_T) {
        float4 v = row[i];
        float vl[4] = {v.x, v.y, v.z, v.w};
        #pragma unroll
        for (int l = 0; l < 4; l++) {
            if (vl[l] > THR) {
                int p = atomicAdd(&g_cnt[b], 1);
                if (p < CAPC) {
                    uint32_t idx = (uint32_t)(i * 4 + l);
                    g_cand[b * CAPC + p] =
                        ((unsigned long long)mono(vl[l]) << 32) | (0xFFFFFFFFu - idx);
                }
            }
        }
    }
}

// ---------------- Phase 2: per-row sort + postprocess + NMS ----------------
__global__ __launch_bounds__(POST_T)
void post_kernel(const float* __restrict__ logits,
                 const float* __restrict__ boxes_in,
                 const float* __restrict__ tsizes,
                 float* __restrict__ out)
{
    __shared__ unsigned long long cand[CAPC];
    __shared__ uint32_t s_hist[256];
    __shared__ int s_digit, s_greater, s_cnt2;
    __shared__ float bx0[K_SEL], by0[K_SEL], bx1[K_SEL], by1[K_SEL];
    __shared__ float barea[K_SEL], sscore[K_SEL];
    __shared__ uint32_t sup[K_SEL][4];
    __shared__ uint32_t keepw[4];

    const int b = blockIdx.x;
    const int tid = threadIdx.x;
    const float4* row = (const float4*)(logits + (size_t)b * QC);

    int n = g_cnt[b];

    if (n >= K_SEL && n <= CAPC) {
        // common path: candidates already in global scratch
        for (int i = tid; i < n; i += POST_T)
            cand[i] = g_cand[b * CAPC + i];
    } else {
        // ---- exact radix-select fallback (statistically never taken) ----
        uint32_t prefix = 0, pmask = 0;
        int need = K_SEL;
        for (int level = 3; level >= 0; level--) {
            for (int d = tid; d < 256; d += POST_T) s_hist[d] = 0;
            __syncthreads();
            for (int i = tid; i < NV; i += POST_T) {
                float4 v = row[i];
                float vl[4] = {v.x, v.y, v.z, v.w};
                #pragma unroll
                for (int l = 0; l < 4; l++) {
                    uint32_t m = mono(vl[l]);
                    if ((m & pmask) == prefix)
                        atomicAdd(&s_hist[(m >> (8 * level)) & 255u], 1u);
                }
            }
            __syncthreads();
            if (tid == 0) {
                int acc = 0, dsel = 0;
                for (int d = 255; d >= 0; d--) {
                    int h = (int)s_hist[d];
                    if (acc + h >= need) { dsel = d; break; }
                    acc += h;
                }
                s_digit = dsel;
                s_greater = acc;
            }
            __syncthreads();
            need -= s_greater;
            prefix |= ((uint32_t)s_digit) << (8 * level);
            pmask  |= 0xFFu << (8 * level);
            __syncthreads();
        }
        if (tid == 0) s_cnt2 = 0;
        __syncthreads();
        for (int i = tid; i < NV; i += POST_T) {
            float4 v = row[i];
            float vl[4] = {v.x, v.y, v.z, v.w};
            #pragma unroll
            for (int l = 0; l < 4; l++) {
                uint32_t m = mono(vl[l]);
                if (m >= prefix) {
                    int p = atomicAdd(&s_cnt2, 1);
                    if (p < CAPC) {
                        uint32_t idx = (uint32_t)(i * 4 + l);
                        cand[p] = ((unsigned long long)m << 32) | (0xFFFFFFFFu - idx);
                    }
                }
            }
        }
        __syncthreads();
        n = min(s_cnt2, CAPC);
    }
    __syncthreads();

    // ---- bitonic sort descending, pad to pow2 ----
    int P = 128;
    while (P < n) P <<= 1;
    for (int i = n + tid; i < P; i += POST_T) cand[i] = 0ULL;
    __syncthreads();
    for (int k = 2; k <= P; k <<= 1) {
        for (int j = k >> 1; j > 0; j >>= 1) {
            for (int i = tid; i < P; i += POST_T) {
                int l = i ^ j;
                if (l > i) {
                    unsigned long long a = cand[i], c2 = cand[l];
                    bool descBlock = ((i & k) == 0);
                    if (descBlock ? (a < c2) : (a > c2)) { cand[i] = c2; cand[l] = a; }
                }
            }
            __syncthreads();
        }
    }

    // ---- top-100 decode: scores, labels, boxes ----
    const int BK = BATCH * K_SEL;   // 25600
    if (tid < K_SEL) {
        unsigned long long e = cand[tid];
        uint32_t m = (uint32_t)(e >> 32);
        uint32_t idx = 0xFFFFFFFFu - (uint32_t)(e & 0xFFFFFFFFu);
        float logit = unmono(m);
        float score = 1.0f / (1.0f + expf(-logit));
        int q = idx / CNUM;
        int lab = idx - q * CNUM;
        const float* bp = boxes_in + ((size_t)b * QNUM + q) * 4;
        float cx = bp[0], cy = bp[1], w = bp[2], h = bp[3];
        float img_h = tsizes[2 * b], img_w = tsizes[2 * b + 1];
        float x0 = (cx - 0.5f * w) * img_w;
        float y0 = (cy - 0.5f * h) * img_h;
        float x1 = (cx + 0.5f * w) * img_w;
        float y1 = (cy + 0.5f * h) * img_h;
        bx0[tid] = x0; by0[tid] = y0; bx1[tid] = x1; by1[tid] = y1;
        barea[tid] = (x1 - x0) * (y1 - y0);
        sscore[tid] = score;

        int o = b * K_SEL + tid;
        out[o] = score;
        out[BK + o] = (float)lab;
        float* ob = out + 2 * BK + (size_t)o * 4;
        ob[0] = x0; ob[1] = y0; ob[2] = x1; ob[3] = y1;
    }
    __syncthreads();

    // ---- NMS: parallel 100x100 suppression bitmask, serial chain as bit ops ----
    if (tid < K_SEL) {
        float x0i = bx0[tid], y0i = by0[tid], x1i = bx1[tid], y1i = by1[tid];
        float ai = barea[tid];
        uint32_t m0 = 0, m1 = 0, m2 = 0, m3 = 0;
        for (int j = tid + 1; j < K_SEL; j++) {
            float lx = fmaxf(x0i, bx0[j]);
            float ly = fmaxf(y0i, by0[j]);
            float rx = fminf(x1i, bx1[j]);
            float ry = fminf(y1i, by1[j]);
            float iw = fmaxf(rx - lx, 0.0f);
            float ih = fmaxf(ry - ly, 0.0f);
            float inter = iw * ih;
            float uni = ai + barea[j] - inter;
            float iou = inter / fmaxf(uni, 1e-9f);
            if (iou > 0.7f) {
                uint32_t bit = 1u << (j & 31);
                switch (j >> 5) {
                    case 0: m0 |= bit; break;
                    case 1: m1 |= bit; break;
                    case 2: m2 |= bit; break;
                    default: m3 |= bit; break;
                }
            }
        }
        sup[tid][0] = m0; sup[tid][1] = m1; sup[tid][2] = m2; sup[tid][3] = m3;
    }
    __syncthreads();
    if (tid == 0) {
        uint32_t k0 = ~0u, k1 = ~0u, k2 = ~0u, k3 = ~0u;
        #pragma unroll 4
        for (int i = 0; i < K_SEL; i++) {
            uint32_t kw = (i < 32) ? k0 : (i < 64) ? k1 : (i < 96) ? k2 : k3;
            if ((kw >> (i & 31)) & 1u) {
                k0 &= ~sup[i][0]; k1 &= ~sup[i][1];
                k2 &= ~sup[i][2]; k3 &= ~sup[i][3];
            }
        }
        keepw[0] = k0; keepw[1] = k1; keepw[2] = k2; keepw[3] = k3;
    }
    __syncthreads();
    if (tid < K_SEL) {
        int o = b * K_SEL + tid;
        bool kb = (keepw[tid >> 5] >> (tid & 31)) & 1u;
        out[6 * BK + o] = (sscore[tid] > 0.3f && kb) ? 1.0f : 0.0f;
    }

    // reset counter for next graph replay (stream-ordered before next scan)
    if (tid == 0) g_cnt[b] = 0;
}

extern "C" void kernel_launch(void* const* d_in, const int* in_sizes, int n_in,
                              void* d_out, int out_size)
{
    const float* logits   = (const float*)d_in[0];   // (256, 900, 91) f32
    const float* boxes_in = (const float*)d_in[1];   // (256, 900, 4)  f32
    const float* tsizes   = (const float*)d_in[2];   // (256, 2)       f32
    float* out = (float*)d_out;
    scan_kernel<<<BATCH * SEGS, SCAN_T>>>(logits);
    post_kernel<<<BATCH, POST_T>>>(logits, d_in ? (const float*)d_in[1] : boxes_in, tsizes, out);
}

// round 3
// speedup vs baseline: 1.0650x; 1.0650x over previous
#include <cuda_runtime.h>
#include <cstdint>

#define BATCH 256
#define QNUM 900
#define CNUM 91
#define QC (QNUM * CNUM)        // 81900
#define NV (QC / 4)             // 20475 float4 per row
#define NV_ALL (BATCH * NV)     // 5241600 float4 total
#define K_SEL 100
#define CAPC 1024
#define THR 2.75f
#define SCAN_CTAS 4096
#define SCAN_T 256
#define SCAN_ITERS 5            // ceil(NV_ALL / (SCAN_CTAS*SCAN_T))
#define POST_T 256

__device__ int g_cnt[BATCH];                         // zero-init; reset by post_kernel
__device__ unsigned long long g_cand[BATCH * CAPC];  // 2 MB scratch

// monotone float<->uint mapping (order-preserving)
__device__ __forceinline__ uint32_t mono(float f) {
    uint32_t u = __float_as_uint(f);
    return u ^ ((u >> 31) ? 0xFFFFFFFFu : 0x80000000u);
}
__device__ __forceinline__ float unmono(uint32_t m) {
    uint32_t u = (m & 0x80000000u) ? (m ^ 0x80000000u) : ~m;
    return __uint_as_float(u);
}

// ---------------- Phase 1: full-chip streaming scan ----------------
__global__ __launch_bounds__(SCAN_T)
void scan_kernel(const float* __restrict__ logits)
{
    const float4* p = (const float4*)logits;
    const int base = blockIdx.x * SCAN_T + threadIdx.x;
    const int stride = SCAN_CTAS * SCAN_T;   // 1048576

    #pragma unroll
    for (int k = 0; k < SCAN_ITERS; k++) {
        int i = base + k * stride;
        if (i < NV_ALL) {
            float4 v = p[i];
            float vl[4] = {v.x, v.y, v.z, v.w};
            #pragma unroll
            for (int l = 0; l < 4; l++) {
                if (vl[l] > THR) {
                    int e = i * 4 + l;           // global element index
                    int b = e / QC;              // row
                    uint32_t idx = (uint32_t)(e - b * QC);
                    int pcount = atomicAdd(&g_cnt[b], 1);
                    if (pcount < CAPC) {
                        g_cand[b * CAPC + pcount] =
                            ((unsigned long long)mono(vl[l]) << 32) | (0xFFFFFFFFu - idx);
                    }
                }
            }
        }
    }
}

// ---------------- Phase 2: per-row rank-select + NMS ----------------
__global__ __launch_bounds__(POST_T)
void post_kernel(const float* __restrict__ logits,
                 const float* __restrict__ boxes_in,
                 const float* __restrict__ tsizes,
                 float* __restrict__ out)
{
    __shared__ unsigned long long cand[CAPC];
    __shared__ unsigned long long topk[K_SEL];
    __shared__ uint32_t s_hist[256];
    __shared__ int s_digit, s_greater, s_cnt2;
    __shared__ float bx0[K_SEL], by0[K_SEL], bx1[K_SEL], by1[K_SEL];
    __shared__ float barea[K_SEL], sscore[K_SEL];
    __shared__ uint4 sup4[K_SEL];
    __shared__ uint32_t keepw[4];

    const int b = blockIdx.x;
    const int tid = threadIdx.x;
    const float4* row = (const float4*)(logits + (size_t)b * QC);

    int n = g_cnt[b];

    if (n >= K_SEL && n <= CAPC) {
        // fast path: candidates already in global scratch
        for (int i = tid; i < n; i += POST_T)
            cand[i] = g_cand[b * CAPC + i];
    } else {
        // ---- exact radix-select fallback (statistically never taken) ----
        uint32_t prefix = 0, pmask = 0;
        int need = K_SEL;
        for (int level = 3; level >= 0; level--) {
            for (int d = tid; d < 256; d += POST_T) s_hist[d] = 0;
            __syncthreads();
            for (int i = tid; i < NV; i += POST_T) {
                float4 v = row[i];
                float vl[4] = {v.x, v.y, v.z, v.w};
                #pragma unroll
                for (int l = 0; l < 4; l++) {
                    uint32_t m = mono(vl[l]);
                    if ((m & pmask) == prefix)
                        atomicAdd(&s_hist[(m >> (8 * level)) & 255u], 1u);
                }
            }
            __syncthreads();
            if (tid == 0) {
                int acc = 0, dsel = 0;
                for (int d = 255; d >= 0; d--) {
                    int h = (int)s_hist[d];
                    if (acc + h >= need) { dsel = d; break; }
                    acc += h;
                }
                s_digit = dsel;
                s_greater = acc;
            }
            __syncthreads();
            need -= s_greater;
            prefix |= ((uint32_t)s_digit) << (8 * level);
            pmask  |= 0xFFu << (8 * level);
            __syncthreads();
        }
        if (tid == 0) s_cnt2 = 0;
        __syncthreads();
        for (int i = tid; i < NV; i += POST_T) {
            float4 v = row[i];
            float vl[4] = {v.x, v.y, v.z, v.w};
            #pragma unroll
            for (int l = 0; l < 4; l++) {
                uint32_t m = mono(vl[l]);
                if (m >= prefix) {
                    int p = atomicAdd(&s_cnt2, 1);
                    if (p < CAPC) {
                        uint32_t idx = (uint32_t)(i * 4 + l);
                        cand[p] = ((unsigned long long)m << 32) | (0xFFFFFFFFu - idx);
                    }
                }
            }
        }
        __syncthreads();
        n = min(s_cnt2, CAPC);
    }
    __syncthreads();

    // ---- rank-by-counting top-100 (no barriers inside; keys unique) ----
    for (int t = tid; t < n; t += POST_T) {
        unsigned long long key = cand[t];
        int rank = 0;
        for (int j = 0; j < n; j++)
            rank += (cand[j] > key);
        if (rank < K_SEL) topk[rank] = key;
    }
    __syncthreads();

    // ---- top-100 decode: scores, labels, boxes ----
    const int BK = BATCH * K_SEL;   // 25600
    if (tid < K_SEL) {
        unsigned long long e = topk[tid];
        uint32_t m = (uint32_t)(e >> 32);
        uint32_t idx = 0xFFFFFFFFu - (uint32_t)(e & 0xFFFFFFFFu);
        float logit = unmono(m);
        float score = 1.0f / (1.0f + expf(-logit));
        int q = idx / CNUM;
        int lab = idx - q * CNUM;
        const float* bp = boxes_in + ((size_t)b * QNUM + q) * 4;
        float cx = bp[0], cy = bp[1], w = bp[2], h = bp[3];
        float img_h = tsizes[2 * b], img_w = tsizes[2 * b + 1];
        float x0 = (cx - 0.5f * w) * img_w;
        float y0 = (cy - 0.5f * h) * img_h;
        float x1 = (cx + 0.5f * w) * img_w;
        float y1 = (cy + 0.5f * h) * img_h;
        bx0[tid] = x0; by0[tid] = y0; bx1[tid] = x1; by1[tid] = y1;
        barea[tid] = (x1 - x0) * (y1 - y0);
        sscore[tid] = score;

        int o = b * K_SEL + tid;
        out[o] = score;
        out[BK + o] = (float)lab;
        float* ob = out + 2 * BK + (size_t)o * 4;
        ob[0] = x0; ob[1] = y0; ob[2] = x1; ob[3] = y1;
    }
    __syncthreads();

    // ---- NMS: parallel 100x100 suppression bitmask, serial chain as bit ops ----
    if (tid < K_SEL) {
        float x0i = bx0[tid], y0i = by0[tid], x1i = bx1[tid], y1i = by1[tid];
        float ai = barea[tid];
        uint32_t m0 = 0, m1 = 0, m2 = 0, m3 = 0;
        for (int j = tid + 1; j < K_SEL; j++) {
            float lx = fmaxf(x0i, bx0[j]);
            float ly = fmaxf(y0i, by0[j]);
            float rx = fminf(x1i, bx1[j]);
            float ry = fminf(y1i, by1[j]);
            float iw = fmaxf(rx - lx, 0.0f);
            float ih = fmaxf(ry - ly, 0.0f);
            float inter = iw * ih;
            float uni = ai + barea[j] - inter;
            float iou = inter / fmaxf(uni, 1e-9f);
            if (iou > 0.7f) {
                uint32_t bit = 1u << (j & 31);
                switch (j >> 5) {
                    case 0: m0 |= bit; break;
                    case 1: m1 |= bit; break;
                    case 2: m2 |= bit; break;
                    default: m3 |= bit; break;
                }
            }
        }
        sup4[tid] = make_uint4(m0, m1, m2, m3);
    }
    __syncthreads();
    if (tid == 0) {
        uint32_t k0 = ~0u, k1 = ~0u, k2 = ~0u, k3 = ~0u;
        #pragma unroll 4
        for (int i = 0; i < K_SEL; i++) {
            uint32_t kw = (i < 32) ? k0 : (i < 64) ? k1 : (i < 96) ? k2 : k3;
            if ((kw >> (i & 31)) & 1u) {
                uint4 s = sup4[i];
                k0 &= ~s.x; k1 &= ~s.y; k2 &= ~s.z; k3 &= ~s.w;
            }
        }
        keepw[0] = k0; keepw[1] = k1; keepw[2] = k2; keepw[3] = k3;
    }
    __syncthreads();
    if (tid < K_SEL) {
        int o = b * K_SEL + tid;
        bool kb = (keepw[tid >> 5] >> (tid & 31)) & 1u;
        out[6 * BK + o] = (sscore[tid] > 0.3f && kb) ? 1.0f : 0.0f;
    }

    // reset counter for next graph replay (stream-ordered before next scan)
    if (tid == 0) g_cnt[b] = 0;
}

extern "C" void kernel_launch(void* const* d_in, const int* in_sizes, int n_in,
                              void* d_out, int out_size)
{
    const float* logits   = (const float*)d_in[0];   // (256, 900, 91) f32
    const float* boxes_in = (const float*)d_in[1];   // (256, 900, 4)  f32
    const float* tsizes   = (const float*)d_in[2];   // (256, 2)       f32
    float* out = (float*)d_out;
    scan_kernel<<<SCAN_CTAS, SCAN_T>>>(logits);
    post_kernel<<<BATCH, POST_T>>>(logits, boxes_in, tsizes, out);
}

// round 4
// speedup vs baseline: 1.1010x; 1.0339x over previous
#include <cuda_runtime.h>
#include <cstdint>

#define BATCH 256
#define QNUM 900
#define CNUM 91
#define QC (QNUM * CNUM)        // 81900
#define NV (QC / 4)             // 20475 float4 per row
#define NV_ALL (BATCH * NV)     // 5241600 float4 total
#define K_SEL 100
#define CAPC 1024
#define THR 2.75f
#define SCAN_CTAS 4096
#define SCAN_T 256
#define SCAN_ITERS 5            // ceil(NV_ALL / (SCAN_CTAS*SCAN_T))
#define POST_T 256

__device__ int g_cnt[BATCH];                         // zero-init; reset by post_kernel
__device__ unsigned long long g_cand[BATCH * CAPC];  // 2 MB scratch

// monotone float<->uint mapping (order-preserving)
__device__ __forceinline__ uint32_t mono(float f) {
    uint32_t u = __float_as_uint(f);
    return u ^ ((u >> 31) ? 0xFFFFFFFFu : 0x80000000u);
}
__device__ __forceinline__ float unmono(uint32_t m) {
    uint32_t u = (m & 0x80000000u) ? (m ^ 0x80000000u) : ~m;
    return __uint_as_float(u);
}

// ---------------- Phase 1: full-chip streaming scan ----------------
__global__ __launch_bounds__(SCAN_T)
void scan_kernel(const float* __restrict__ logits)
{
    const float4* p = (const float4*)(logits);
    const int base = blockIdx.x * SCAN_T + threadIdx.x;
    const int stride = SCAN_CTAS * SCAN_T;   // 1048576

    #pragma unroll
    for (int k = 0; k < SCAN_ITERS; k++) {
        int i = base + k * stride;
        if (i < NV_ALL) {
            float4 v = p[i];
            // cheap filter: 3 FMNMX + 1 FSETP per 16 bytes
            float vmax = fmaxf(fmaxf(v.x, v.y), fmaxf(v.z, v.w));
            if (vmax > THR) {
                float vl[4] = {v.x, v.y, v.z, v.w};
                #pragma unroll
                for (int l = 0; l < 4; l++) {
                    if (vl[l] > THR) {
                        int e = i * 4 + l;           // global element index
                        int b = e / QC;              // row
                        uint32_t idx = (uint32_t)(e - b * QC);
                        int pcount = atomicAdd(&g_cnt[b], 1);
                        if (pcount < CAPC) {
                            g_cand[b * CAPC + pcount] =
                                ((unsigned long long)mono(vl[l]) << 32) | (0xFFFFFFFFu - idx);
                        }
                    }
                }
            }
        }
    }
}

// ---------------- Phase 2: per-row rank-select + NMS ----------------
__global__ __launch_bounds__(POST_T)
void post_kernel(const float* __restrict__ logits,
                 const float* __restrict__ boxes_in,
                 const float* __restrict__ tsizes,
                 float* __restrict__ out)
{
    __shared__ unsigned long long cand[CAPC + 8];
    __shared__ unsigned long long topk[K_SEL];
    __shared__ uint32_t s_hist[256];
    __shared__ int s_digit, s_greater, s_cnt2;
    __shared__ float bx0[K_SEL], by0[K_SEL], bx1[K_SEL], by1[K_SEL];
    __shared__ float barea[K_SEL], sscore[K_SEL];
    __shared__ uint4 sup4[K_SEL];
    __shared__ uint32_t keepw[4];

    const int b = blockIdx.x;
    const int tid = threadIdx.x;
    const float4* row = (const float4*)(logits + (size_t)b * QC);

    int n = g_cnt[b];

    if (n >= K_SEL && n <= CAPC) {
        // fast path: candidates already in global scratch
        for (int i = tid; i < n; i += POST_T)
            cand[i] = g_cand[b * CAPC + i];
    } else {
        // ---- exact radix-select fallback (statistically never taken) ----
        uint32_t prefix = 0, pmask = 0;
        int need = K_SEL;
        for (int level = 3; level >= 0; level--) {
            for (int d = tid; d < 256; d += POST_T) s_hist[d] = 0;
            __syncthreads();
            for (int i = tid; i < NV; i += POST_T) {
                float4 v = row[i];
                float vl[4] = {v.x, v.y, v.z, v.w};
                #pragma unroll
                for (int l = 0; l < 4; l++) {
                    uint32_t m = mono(vl[l]);
                    if ((m & pmask) == prefix)
                        atomicAdd(&s_hist[(m >> (8 * level)) & 255u], 1u);
                }
            }
            __syncthreads();
            if (tid == 0) {
                int acc = 0, dsel = 0;
                for (int d = 255; d >= 0; d--) {
                    int h = (int)s_hist[d];
                    if (acc + h >= need) { dsel = d; break; }
                    acc += h;
                }
                s_digit = dsel;
                s_greater = acc;
            }
            __syncthreads();
            need -= s_greater;
            prefix |= ((uint32_t)s_digit) << (8 * level);
            pmask  |= 0xFFu << (8 * level);
            __syncthreads();
        }
        if (tid == 0) s_cnt2 = 0;
        __syncthreads();
        for (int i = tid; i < NV; i += POST_T) {
            float4 v = row[i];
            float vl[4] = {v.x, v.y, v.z, v.w};
            #pragma unroll
            for (int l = 0; l < 4; l++) {
                uint32_t m = mono(vl[l]);
                if (m >= prefix) {
                    int p = atomicAdd(&s_cnt2, 1);
                    if (p < CAPC) {
                        uint32_t idx = (uint32_t)(i * 4 + l);
                        cand[p] = ((unsigned long long)m << 32) | (0xFFFFFFFFu - idx);
                    }
                }
            }
        }
        __syncthreads();
        n = min(s_cnt2, CAPC);
    }
    // pad to multiple of 8 with zero keys (0 < any real key; never > key)
    {
        int n8 = (n + 7) & ~7;
        if (tid < 8 && n + tid < n8 + 8) {
            int q = n + tid;
            if (q < CAPC + 8) cand[q] = 0ULL;
        }
        __syncthreads();

        // ---- rank-by-counting top-100, unroll-8 (keys unique, barriers none) ----
        int n8b = n8;
        for (int t = tid; t < n; t += POST_T) {
            unsigned long long key = cand[t];
            int rank = 0;
            for (int j = 0; j < n8b; j += 8) {
                unsigned long long a0 = cand[j + 0];
                unsigned long long a1 = cand[j + 1];
                unsigned long long a2 = cand[j + 2];
                unsigned long long a3 = cand[j + 3];
                unsigned long long a4 = cand[j + 4];
                unsigned long long a5 = cand[j + 5];
                unsigned long long a6 = cand[j + 6];
                unsigned long long a7 = cand[j + 7];
                rank += (int)(a0 > key) + (int)(a1 > key) + (int)(a2 > key) + (int)(a3 > key)
                      + (int)(a4 > key) + (int)(a5 > key) + (int)(a6 > key) + (int)(a7 > key);
            }
            if (rank < K_SEL) topk[rank] = key;
        }
    }
    __syncthreads();

    // ---- top-100 decode: scores, labels, boxes ----
    const int BK = BATCH * K_SEL;   // 25600
    if (tid < K_SEL) {
        unsigned long long e = topk[tid];
        uint32_t m = (uint32_t)(e >> 32);
        uint32_t idx = 0xFFFFFFFFu - (uint32_t)(e & 0xFFFFFFFFu);
        float logit = unmono(m);
        float score = 1.0f / (1.0f + expf(-logit));
        int q = idx / CNUM;
        int lab = idx - q * CNUM;
        const float* bp = boxes_in + ((size_t)b * QNUM + q) * 4;
        float cx = bp[0], cy = bp[1], w = bp[2], h = bp[3];
        float img_h = tsizes[2 * b], img_w = tsizes[2 * b + 1];
        float x0 = (cx - 0.5f * w) * img_w;
        float y0 = (cy - 0.5f * h) * img_h;
        float x1 = (cx + 0.5f * w) * img_w;
        float y1 = (cy + 0.5f * h) * img_h;
        bx0[tid] = x0; by0[tid] = y0; bx1[tid] = x1; by1[tid] = y1;
        barea[tid] = (x1 - x0) * (y1 - y0);
        sscore[tid] = score;

        int o = b * K_SEL + tid;
        out[o] = score;
        out[BK + o] = (float)lab;
        float* ob = out + 2 * BK + (size_t)o * 4;
        ob[0] = x0; ob[1] = y0; ob[2] = x1; ob[3] = y1;
    }
    __syncthreads();

    // ---- NMS: fixed-trip 100x100 suppression bitmask ----
    if (tid < K_SEL) {
        float x0i = bx0[tid], y0i = by0[tid], x1i = bx1[tid], y1i = by1[tid];
        float ai = barea[tid];
        uint32_t mm[4] = {0, 0, 0, 0};
        #pragma unroll 4
        for (int j = 0; j < K_SEL; j++) {
            float lx = fmaxf(x0i, bx0[j]);
            float ly = fmaxf(y0i, by0[j]);
            float rx = fminf(x1i, bx1[j]);
            float ry = fminf(y1i, by1[j]);
            float iw = fmaxf(rx - lx, 0.0f);
            float ih = fmaxf(ry - ly, 0.0f);
            float inter = iw * ih;
            float uni = ai + barea[j] - inter;
            float iou = inter / fmaxf(uni, 1e-9f);
            if (iou > 0.7f && j > tid)
                mm[j >> 5] |= 1u << (j & 31);
        }
        sup4[tid] = make_uint4(mm[0], mm[1], mm[2], mm[3]);
    }
    __syncthreads();

    // ---- serial greedy chain: static segments + LDS prefetch ----
    if (tid == 0) {
        uint32_t k0 = ~0u, k1 = ~0u, k2 = ~0u, k3 = ~0u;
        uint4 s = sup4[0];
        #pragma unroll 1
        for (int i = 0; i < 32; i++) {
            uint4 sn = sup4[i + 1];
            if ((k0 >> i) & 1u) { k0 &= ~s.x; k1 &= ~s.y; k2 &= ~s.z; k3 &= ~s.w; }
            s = sn;
        }
        #pragma unroll 1
        for (int i = 32; i < 64; i++) {
            uint4 sn = sup4[i + 1];
            if ((k1 >> (i - 32)) & 1u) { k0 &= ~s.x; k1 &= ~s.y; k2 &= ~s.z; k3 &= ~s.w; }
            s = sn;
        }
        #pragma unroll 1
        for (int i = 64; i < 96; i++) {
            uint4 sn = sup4[i + 1];
            if ((k2 >> (i - 64)) & 1u) { k0 &= ~s.x; k1 &= ~s.y; k2 &= ~s.z; k3 &= ~s.w; }
            s = sn;
        }
        #pragma unroll 1
        for (int i = 96; i < K_SEL; i++) {
            uint4 sn = (i + 1 < K_SEL) ? sup4[i + 1] : make_uint4(0, 0, 0, 0);
            if ((k3 >> (i - 96)) & 1u) { k0 &= ~s.x; k1 &= ~s.y; k2 &= ~s.z; k3 &= ~s.w; }
            s = sn;
        }
        keepw[0] = k0; keepw[1] = k1; keepw[2] = k2; keepw[3] = k3;
    }
    __syncthreads();
    if (tid < K_SEL) {
        int o = b * K_SEL + tid;
        bool kb = (keepw[tid >> 5] >> (tid & 31)) & 1u;
        out[6 * BK + o] = (sscore[tid] > 0.3f && kb) ? 1.0f : 0.0f;
    }

    // reset counter for next graph replay (stream-ordered before next scan)
    if (tid == 0) g_cnt[b] = 0;
}

extern "C" void kernel_launch(void* const* d_in, const int* in_sizes, int n_in,
                              void* d_out, int out_size)
{
    const float* logits   = (const float*)d_in[0];   // (256, 900, 91) f32
    const float* boxes_in = (const float*)d_in[1];   // (256, 900, 4)  f32
    const float* tsizes   = (const float*)d_in[2];   // (256, 2)       f32
    float* out = (float*)d_out;
    scan_kernel<<<SCAN_CTAS, SCAN_T>>>(logits);
    post_kernel<<<BATCH, POST_T>>>(logits, boxes_in, tsizes, out);
}